// round 1
// baseline (speedup 1.0000x reference)
#include <cuda_runtime.h>
#include <cuda_bf16.h>
#include <cstdint>

// Problem: y[b,s,o] = mask[b,s] ? x[b,s,:]·W_v[o,:] : x[b,s,:]·W_t[o,:]
// M = 32768 tokens, K = 1024, N = 1024. fp32 in/out.
// Strategy: tf32 mma.sync dual-accumulator GEMM, mask select in epilogue.

#define M_TOTAL 32768
#define K_DIM   1024
#define N_DIM   1024
#define BM 128
#define BN 64
#define BK 32
#define THREADS 256
#define SA_STRIDE 36   // padded stride (floats): (4*row+col)%32 conflict-free

// mask dtype detection flag: 1 = uint8 (numpy bool), 0 = int32
__device__ int g_mask_is_u8;

__global__ void detect_mask_kernel(const unsigned char* __restrict__ m) {
    __shared__ int found;
    if (threadIdx.x == 0) found = 0;
    __syncthreads();
    int local = 0;
    // Probe bytes at offsets 4i+1..4i+3 within the first 32768 bytes (safe for
    // both layouts). int32 0/1 data has all-zero there; uint8 random bools don't.
    for (int i = threadIdx.x; i < 8192; i += blockDim.x) {
        if (m[4 * i + 1] | m[4 * i + 2] | m[4 * i + 3]) local = 1;
    }
    if (local) atomicOr(&found, 1);
    __syncthreads();
    if (threadIdx.x == 0) g_mask_is_u8 = found;
}

__device__ __forceinline__ float to_tf32(float f) {
    uint32_t o;
    asm("cvt.rna.tf32.f32 %0, %1;" : "=r"(o) : "f"(f));
    return __uint_as_float(o);
}

__device__ __forceinline__ void mma_tf32(float* d, const uint32_t* a, const uint32_t* b) {
    asm volatile(
        "mma.sync.aligned.m16n8k8.row.col.f32.tf32.tf32.f32 "
        "{%0,%1,%2,%3}, {%4,%5,%6,%7}, {%8,%9}, {%0,%1,%2,%3};"
        : "+f"(d[0]), "+f"(d[1]), "+f"(d[2]), "+f"(d[3])
        : "r"(a[0]), "r"(a[1]), "r"(a[2]), "r"(a[3]), "r"(b[0]), "r"(b[1]));
}

__global__ __launch_bounds__(THREADS, 1)
void dual_gemm_kernel(const float* __restrict__ x,
                      const unsigned char* __restrict__ mask,
                      const float* __restrict__ Wv,
                      const float* __restrict__ Wt,
                      float* __restrict__ out)
{
    __shared__ float sA[BM * SA_STRIDE];
    __shared__ float sBv[BN * SA_STRIDE];
    __shared__ float sBt[BN * SA_STRIDE];

    const int t = threadIdx.x;
    const int blockM = blockIdx.x * BM;
    const int blockN = blockIdx.y * BN;

    const int warp = t >> 5;
    const int lane = t & 31;
    const int wm = (warp >> 1) * 32;   // 4 warps along M
    const int wn = (warp & 1) * 32;    // 2 warps along N
    const int grp = lane >> 2;         // 0..7
    const int qid = lane & 3;          // 0..3

    float accv[2][4][4];
    float acct[2][4][4];
    #pragma unroll
    for (int i = 0; i < 2; i++)
        #pragma unroll
        for (int j = 0; j < 4; j++)
            #pragma unroll
            for (int c = 0; c < 4; c++) { accv[i][j][c] = 0.f; acct[i][j][c] = 0.f; }

    // register staging for double buffering
    float4 ra[4], rv[2], rt[2];

    auto LOAD = [&](int kb) {
        #pragma unroll
        for (int i = 0; i < 4; i++) {
            int f = t + i * THREADS;          // 0..1023
            int r = f >> 3;                   // 0..127
            int c = (f & 7) * 4;              // 0..28
            ra[i] = *(const float4*)(x + (size_t)(blockM + r) * K_DIM + kb + c);
        }
        #pragma unroll
        for (int i = 0; i < 2; i++) {
            int f = t + i * THREADS;          // 0..511
            int r = f >> 3;                   // 0..63
            int c = (f & 7) * 4;
            rv[i] = *(const float4*)(Wv + (size_t)(blockN + r) * K_DIM + kb + c);
            rt[i] = *(const float4*)(Wt + (size_t)(blockN + r) * K_DIM + kb + c);
        }
    };

    auto STORE = [&]() {
        #pragma unroll
        for (int i = 0; i < 4; i++) {
            int f = t + i * THREADS;
            int r = f >> 3;
            int c = (f & 7) * 4;
            float4 v = ra[i];
            float4 w = make_float4(to_tf32(v.x), to_tf32(v.y), to_tf32(v.z), to_tf32(v.w));
            *(float4*)(sA + r * SA_STRIDE + c) = w;
        }
        #pragma unroll
        for (int i = 0; i < 2; i++) {
            int f = t + i * THREADS;
            int r = f >> 3;
            int c = (f & 7) * 4;
            float4 v = rv[i];
            *(float4*)(sBv + r * SA_STRIDE + c) =
                make_float4(to_tf32(v.x), to_tf32(v.y), to_tf32(v.z), to_tf32(v.w));
            v = rt[i];
            *(float4*)(sBt + r * SA_STRIDE + c) =
                make_float4(to_tf32(v.x), to_tf32(v.y), to_tf32(v.z), to_tf32(v.w));
        }
    };

    auto COMPUTE = [&]() {
        #pragma unroll
        for (int ks = 0; ks < 4; ks++) {
            const int kb2 = ks * 8;
            uint32_t a[2][4];
            #pragma unroll
            for (int i = 0; i < 2; i++) {
                int row = wm + i * 16 + grp;
                a[i][0] = __float_as_uint(sA[row * SA_STRIDE + kb2 + qid]);
                a[i][1] = __float_as_uint(sA[(row + 8) * SA_STRIDE + kb2 + qid]);
                a[i][2] = __float_as_uint(sA[row * SA_STRIDE + kb2 + qid + 4]);
                a[i][3] = __float_as_uint(sA[(row + 8) * SA_STRIDE + kb2 + qid + 4]);
            }
            uint32_t bv[4][2], bt[4][2];
            #pragma unroll
            for (int j = 0; j < 4; j++) {
                int n = wn + j * 8 + grp;
                bv[j][0] = __float_as_uint(sBv[n * SA_STRIDE + kb2 + qid]);
                bv[j][1] = __float_as_uint(sBv[n * SA_STRIDE + kb2 + qid + 4]);
                bt[j][0] = __float_as_uint(sBt[n * SA_STRIDE + kb2 + qid]);
                bt[j][1] = __float_as_uint(sBt[n * SA_STRIDE + kb2 + qid + 4]);
            }
            #pragma unroll
            for (int i = 0; i < 2; i++)
                #pragma unroll
                for (int j = 0; j < 4; j++) {
                    mma_tf32(accv[i][j], a[i], bv[j]);
                    mma_tf32(acct[i][j], a[i], bt[j]);
                }
        }
    };

    // prologue: tile 0
    LOAD(0);
    STORE();
    __syncthreads();

    const int NKT = K_DIM / BK;  // 32
    for (int kt = 0; kt < NKT; kt++) {
        if (kt < NKT - 1) LOAD((kt + 1) * BK);   // overlap gmem with compute
        COMPUTE();
        if (kt < NKT - 1) {
            __syncthreads();
            STORE();
            __syncthreads();
        }
    }

    // epilogue: per-row mask select
    const int is_u8 = g_mask_is_u8;
    const int* mask_i32 = (const int*)mask;

    #pragma unroll
    for (int i = 0; i < 2; i++) {
        int r0 = blockM + wm + i * 16 + grp;
        int r1 = r0 + 8;
        bool m0 = is_u8 ? (mask[r0] != 0) : (mask_i32[r0] != 0);
        bool m1 = is_u8 ? (mask[r1] != 0) : (mask_i32[r1] != 0);
        #pragma unroll
        for (int j = 0; j < 4; j++) {
            int col = blockN + wn + j * 8 + qid * 2;
            float2 o0, o1;
            if (m0) { o0.x = accv[i][j][0]; o0.y = accv[i][j][1]; }
            else    { o0.x = acct[i][j][0]; o0.y = acct[i][j][1]; }
            if (m1) { o1.x = accv[i][j][2]; o1.y = accv[i][j][3]; }
            else    { o1.x = acct[i][j][2]; o1.y = acct[i][j][3]; }
            *(float2*)(out + (size_t)r0 * N_DIM + col) = o0;
            *(float2*)(out + (size_t)r1 * N_DIM + col) = o1;
        }
    }
}

extern "C" void kernel_launch(void* const* d_in, const int* in_sizes, int n_in,
                              void* d_out, int out_size)
{
    const float*         x    = (const float*)d_in[0];
    const unsigned char* mask = (const unsigned char*)d_in[1];
    const float*         Wv   = (const float*)d_in[2];
    const float*         Wt   = (const float*)d_in[3];
    float*               out  = (float*)d_out;

    detect_mask_kernel<<<1, 256>>>(mask);

    dim3 grid(M_TOTAL / BM, N_DIM / BN);  // 256 x 16
    dual_gemm_kernel<<<grid, THREADS>>>(x, mask, Wv, Wt, out);
}

// round 3
// speedup vs baseline: 1.8990x; 1.8990x over previous
#include <cuda_runtime.h>
#include <cstdint>

// y[m,n] = mask[m] ? x[m,:]·W_v[n,:] : x[m,:]·W_t[n,:]
// Mask-partitioned single GEMM: rows permuted so each 128-row tile uses
// exactly one weight matrix. tf32 mma.sync (fallback HMMA path; tcgen05 is
// rejected by this harness's compute_103 PTX target).

#define M_TOTAL 32768
#define K_DIM   1024
#define N_DIM   1024
#define BM 128
#define BN 128
#define BK 16
#define STAGES 4
#define NK (K_DIM / BK)          // 64
#define THREADS 128
#define M_PAD 32896              // 257 tiles * 128 (room for segment padding)
#define ROW_STRIDE 20            // smem row stride in floats (80B: conflict-free)
#define STAGE_BYTES (2 * BM * ROW_STRIDE * 4)   // A + B = 20480 B
#define B_OFF (BM * ROW_STRIDE * 4)             // 10240 B
#define DYN_SMEM (STAGES * STAGE_BYTES)         // 81920 B

// ------------------------------------------------------------- device state
__device__ float g_x[(size_t)M_PAD * K_DIM];    // permuted, tf32-rounded x
__device__ float g_wv[(size_t)N_DIM * K_DIM];   // tf32-rounded weights
__device__ float g_wt[(size_t)N_DIM * K_DIM];
__device__ int   g_perm[M_PAD];                 // slot -> source row (-1 dead)
__device__ int   g_nv, g_cv, g_ct;
__device__ int   g_mask_is_u8;

// ------------------------------------------------------------- helpers
__device__ __forceinline__ float to_tf32(float f) {
    uint32_t o;
    asm("cvt.rna.tf32.f32 %0, %1;" : "=r"(o) : "f"(f));
    return __uint_as_float(o);
}

__device__ __forceinline__ bool mask_at(const unsigned char* m, int i) {
    return g_mask_is_u8 ? (m[i] != 0) : (((const int*)m)[i] != 0);
}

__device__ __forceinline__ uint32_t smem_u32(const void* p) {
    uint32_t a;
    asm("{ .reg .u64 t; cvta.to.shared.u64 t, %1; cvt.u32.u64 %0, t; }"
        : "=r"(a) : "l"(p));
    return a;
}

__device__ __forceinline__ void cp16(uint32_t saddr, const void* g) {
    asm volatile("cp.async.cg.shared.global [%0], [%1], 16;"
                 :: "r"(saddr), "l"(g) : "memory");
}

__device__ __forceinline__ void mma_tf32(float* d, const float* a, const float* b) {
    asm volatile(
        "mma.sync.aligned.m16n8k8.row.col.f32.tf32.tf32.f32 "
        "{%0,%1,%2,%3}, {%4,%5,%6,%7}, {%8,%9}, {%0,%1,%2,%3};"
        : "+f"(d[0]), "+f"(d[1]), "+f"(d[2]), "+f"(d[3])
        : "r"(__float_as_uint(a[0])), "r"(__float_as_uint(a[1])),
          "r"(__float_as_uint(a[2])), "r"(__float_as_uint(a[3])),
          "r"(__float_as_uint(b[0])), "r"(__float_as_uint(b[1])));
}

// ------------------------------------------------------------- prep kernels
// K0: detect mask dtype, reset counters, clear perm
__global__ void k0_init(const unsigned char* __restrict__ m) {
    __shared__ int found;
    int tid = threadIdx.x;
    if (tid == 0) { found = 0; g_nv = 0; g_cv = 0; g_ct = 0; }
    __syncthreads();
    int local = 0;
    for (int i = tid; i < 8192; i += 1024)
        if (m[4 * i + 1] | m[4 * i + 2] | m[4 * i + 3]) local = 1;
    if (local) atomicOr(&found, 1);
    for (int i = tid; i < M_PAD; i += 1024) g_perm[i] = -1;
    __syncthreads();
    if (tid == 0) g_mask_is_u8 = found;
}

// K1: count visual rows
__global__ void k1_count(const unsigned char* __restrict__ m) {
    int row = blockIdx.x * 256 + threadIdx.x;
    bool mv = mask_at(m, row);
    unsigned bal = __ballot_sync(0xffffffffu, mv);
    if ((threadIdx.x & 31) == 0) atomicAdd(&g_nv, __popc(bal));
}

// K2: assign permutation slots (visual -> [0,nv), text -> [nv_pad, ...))
__global__ void k2_assign(const unsigned char* __restrict__ m) {
    __shared__ int s_v[8], s_t[8];
    __shared__ int s_baseV, s_baseT;
    int tid = threadIdx.x;
    int row = blockIdx.x * 256 + tid;
    int warp = tid >> 5, lane = tid & 31;
    bool mv = mask_at(m, row);
    unsigned bal = __ballot_sync(0xffffffffu, mv);
    int lpv = __popc(bal & ((1u << lane) - 1));
    int lpt = lane - lpv;
    if (lane == 0) { s_v[warp] = __popc(bal); s_t[warp] = 32 - __popc(bal); }
    __syncthreads();
    if (tid == 0) {
        int av = 0, at = 0;
        #pragma unroll
        for (int w = 0; w < 8; w++) {
            int tv = s_v[w]; s_v[w] = av; av += tv;
            int tt = s_t[w]; s_t[w] = at; at += tt;
        }
        s_baseV = atomicAdd(&g_cv, av);
        s_baseT = atomicAdd(&g_ct, at);
    }
    __syncthreads();
    int pad = (g_nv + 127) & ~127;
    int slot = mv ? (s_baseV + s_v[warp] + lpv)
                  : (pad + s_baseT + s_t[warp] + lpt);
    g_perm[slot] = row;
}

// K3: gather + tf32-round x into permuted scratch (one block per slot)
__global__ void k3_xconv(const float* __restrict__ x) {
    int slot = blockIdx.x;
    int src = g_perm[slot];
    if (src < 0) return;
    const float4* in  = (const float4*)(x + (size_t)src * K_DIM);
    float4*       dst = (float4*)(g_x + (size_t)slot * K_DIM);
    float4 v = in[threadIdx.x];
    dst[threadIdx.x] = make_float4(to_tf32(v.x), to_tf32(v.y),
                                   to_tf32(v.z), to_tf32(v.w));
}

// K4: tf32-round both weight matrices
__global__ void k4_wconv(const float* __restrict__ Wv, const float* __restrict__ Wt) {
    const float4* src = (const float4*)(blockIdx.y ? Wt : Wv);
    float4*       dst = (float4*)(blockIdx.y ? g_wt : g_wv);
    int i = blockIdx.x * 256 + threadIdx.x;
    float4 v = src[i];
    dst[i] = make_float4(to_tf32(v.x), to_tf32(v.y), to_tf32(v.z), to_tf32(v.w));
}

// ------------------------------------------------------------- GEMM
extern __shared__ char dsmem[];

__global__ __launch_bounds__(THREADS, 2)
void gemm_kernel(float* __restrict__ out)
{
    const int tid  = threadIdx.x;
    const int warp = tid >> 5;
    const int lane = tid & 31;
    const int grp  = lane >> 2;      // 0..7
    const int qid  = lane & 3;       // 0..3
    const int wm   = (warp >> 1) * 64;
    const int wn   = (warp & 1) * 64;
    const int blockN = blockIdx.x * BN;
    const int blockM = blockIdx.y * BM;

    const int pad = (g_nv + 127) & ~127;
    const float* gA = g_x + (size_t)blockM * K_DIM;
    const float* gB = ((blockM < pad) ? g_wv : g_wt) + (size_t)blockN * K_DIM;

    const uint32_t sbase = smem_u32(dsmem);
    float* sm = (float*)dsmem;

    float acc[4][8][4];
    #pragma unroll
    for (int i = 0; i < 4; i++)
        #pragma unroll
        for (int j = 0; j < 8; j++)
            #pragma unroll
            for (int c = 0; c < 4; c++) acc[i][j][c] = 0.f;

    auto ISSUE = [&](int kt) {
        const int kb = kt * BK;
        const uint32_t sst = sbase + (kt & (STAGES - 1)) * STAGE_BYTES;
        #pragma unroll
        for (int q = 0; q < 4; q++) {
            int c = tid + q * THREADS;          // 0..511
            int row = c >> 2, off = (c & 3) * 4;
            cp16(sst + (uint32_t)(row * ROW_STRIDE + off) * 4,
                 gA + (size_t)row * K_DIM + kb + off);
        }
        #pragma unroll
        for (int q = 0; q < 4; q++) {
            int c = tid + q * THREADS;
            int row = c >> 2, off = (c & 3) * 4;
            cp16(sst + B_OFF + (uint32_t)(row * ROW_STRIDE + off) * 4,
                 gB + (size_t)row * K_DIM + kb + off);
        }
        asm volatile("cp.async.commit_group;" ::: "memory");
    };

    auto COMPUTE = [&](int s) {
        const float* sA = sm + s * (STAGE_BYTES / 4);
        const float* sB = sA + (B_OFF / 4);
        #pragma unroll
        for (int ks = 0; ks < 2; ks++) {
            const int k0 = ks * 8 + qid;
            float a[4][4];
            #pragma unroll
            for (int i = 0; i < 4; i++) {
                int r = wm + i * 16 + grp;
                a[i][0] = sA[r * ROW_STRIDE + k0];
                a[i][1] = sA[(r + 8) * ROW_STRIDE + k0];
                a[i][2] = sA[r * ROW_STRIDE + k0 + 4];
                a[i][3] = sA[(r + 8) * ROW_STRIDE + k0 + 4];
            }
            float b[8][2];
            #pragma unroll
            for (int j = 0; j < 8; j++) {
                int n = wn + j * 8 + grp;
                b[j][0] = sB[n * ROW_STRIDE + k0];
                b[j][1] = sB[n * ROW_STRIDE + k0 + 4];
            }
            #pragma unroll
            for (int i = 0; i < 4; i++)
                #pragma unroll
                for (int j = 0; j < 8; j++)
                    mma_tf32(acc[i][j], a[i], b[j]);
        }
    };

    ISSUE(0); ISSUE(1); ISSUE(2);

    for (int kt = 0; kt < NK; kt++) {
        asm volatile("cp.async.wait_group %0;" :: "n"(STAGES - 2) : "memory");
        __syncthreads();
        if (kt + STAGES - 1 < NK) ISSUE(kt + STAGES - 1);
        COMPUTE(kt & (STAGES - 1));
    }

    // epilogue: scatter rows through perm
    #pragma unroll
    for (int i = 0; i < 4; i++) {
        int r = wm + i * 16 + grp;
        int d0 = g_perm[blockM + r];
        int d1 = g_perm[blockM + r + 8];
        #pragma unroll
        for (int j = 0; j < 8; j++) {
            int col = blockN + wn + j * 8 + qid * 2;
            if (d0 >= 0)
                *(float2*)(out + (size_t)d0 * N_DIM + col) =
                    make_float2(acc[i][j][0], acc[i][j][1]);
            if (d1 >= 0)
                *(float2*)(out + (size_t)d1 * N_DIM + col) =
                    make_float2(acc[i][j][2], acc[i][j][3]);
        }
    }
}

// ------------------------------------------------------------- launch
extern "C" void kernel_launch(void* const* d_in, const int* in_sizes, int n_in,
                              void* d_out, int out_size)
{
    const float*         x    = (const float*)d_in[0];
    const unsigned char* mask = (const unsigned char*)d_in[1];
    const float*         Wv   = (const float*)d_in[2];
    const float*         Wt   = (const float*)d_in[3];
    float*               out  = (float*)d_out;

    static bool attr_set = false;
    if (!attr_set) {
        cudaFuncSetAttribute(gemm_kernel,
                             cudaFuncAttributeMaxDynamicSharedMemorySize, DYN_SMEM);
        attr_set = true;
    }

    k0_init<<<1, 1024>>>(mask);
    k1_count<<<M_TOTAL / 256, 256>>>(mask);
    k2_assign<<<M_TOTAL / 256, 256>>>(mask);
    k3_xconv<<<M_PAD, 256>>>(x);
    k4_wconv<<<dim3((N_DIM * K_DIM) / (256 * 4), 2), 256>>>(Wv, Wt);
    gemm_kernel<<<dim3(N_DIM / BN, M_PAD / BM), THREADS, DYN_SMEM>>>(out);
}

// round 4
// speedup vs baseline: 4.6438x; 2.4454x over previous
#include <cuda_runtime.h>
#include <cuda_fp16.h>
#include <cstdint>

// y[m,n] = mask[m] ? x[m,:]·W_v[n,:] : x[m,:]·W_t[n,:]
// Mask-partitioned single GEMM, fp16 m16n8k16 mma.sync, fp32 accumulate.
// x and W are pre-converted to fp16 in *MMA fragment order* so the GEMM's
// smem loads are 1 LDS.128 per A-frag / 1 LDS.64 per B-frag and cp.async
// is a pure linear copy (no swizzle).

#define M_TOTAL 32768
#define K_DIM   1024
#define N_DIM   1024
#define BM 128
#define BN 128
#define BK 32
#define STAGES 4
#define NK (K_DIM / BK)              // 32 k-tiles
#define THREADS 128
#define M_PAD 32896                  // 257 tiles * 128
#define NMT (M_PAD / BM)             // 257

#define PANEL_H  4096                // halves per 8KB panel (128 rows x 32 k)
#define APANEL_B 8192
#define STAGE_B  16384               // A panel + B panel
#define DYN_SMEM (STAGES * STAGE_B)  // 64 KB

// ------------------------------------------------------------- device state
__device__ __half g_x[(size_t)M_PAD * K_DIM];    // [mtile][kpanel][frag order]
__device__ __half g_wv[(size_t)N_DIM * K_DIM];   // [ntile][kpanel][frag order]
__device__ __half g_wt[(size_t)N_DIM * K_DIM];
__device__ int   g_perm[M_PAD];                  // slot -> source row (-1 dead)
__device__ int   g_nv, g_cv, g_ct;
__device__ int   g_mask_is_u8;

// ------------------------------------------------------------- helpers
__device__ __forceinline__ bool mask_at(const unsigned char* m, int i) {
    return g_mask_is_u8 ? (m[i] != 0) : (((const int*)m)[i] != 0);
}

__device__ __forceinline__ uint32_t smem_u32(const void* p) {
    uint32_t a;
    asm("{ .reg .u64 t; cvta.to.shared.u64 t, %1; cvt.u32.u64 %0, t; }"
        : "=r"(a) : "l"(p));
    return a;
}

__device__ __forceinline__ void cp16(uint32_t saddr, const void* g) {
    asm volatile("cp.async.cg.shared.global [%0], [%1], 16;"
                 :: "r"(saddr), "l"(g) : "memory");
}

__device__ __forceinline__ void mma_f16(float* d, const uint32_t* a, const uint32_t* b) {
    asm volatile(
        "mma.sync.aligned.m16n8k16.row.col.f32.f16.f16.f32 "
        "{%0,%1,%2,%3}, {%4,%5,%6,%7}, {%8,%9}, {%0,%1,%2,%3};"
        : "+f"(d[0]), "+f"(d[1]), "+f"(d[2]), "+f"(d[3])
        : "r"(a[0]), "r"(a[1]), "r"(a[2]), "r"(a[3]), "r"(b[0]), "r"(b[1]));
}

// ------------------------------------------------------------- prep kernels
__global__ void k0_init(const unsigned char* __restrict__ m) {
    __shared__ int found;
    int tid = threadIdx.x;
    if (tid == 0) { found = 0; g_nv = 0; g_cv = 0; g_ct = 0; }
    __syncthreads();
    int local = 0;
    for (int i = tid; i < 8192; i += 1024)
        if (m[4 * i + 1] | m[4 * i + 2] | m[4 * i + 3]) local = 1;
    if (local) atomicOr(&found, 1);
    for (int i = tid; i < M_PAD; i += 1024) g_perm[i] = -1;
    __syncthreads();
    if (tid == 0) g_mask_is_u8 = found;
}

__global__ void k1_count(const unsigned char* __restrict__ m) {
    int row = blockIdx.x * 256 + threadIdx.x;
    bool mv = mask_at(m, row);
    unsigned bal = __ballot_sync(0xffffffffu, mv);
    if ((threadIdx.x & 31) == 0) atomicAdd(&g_nv, __popc(bal));
}

__global__ void k2_assign(const unsigned char* __restrict__ m) {
    __shared__ int s_v[8], s_t[8];
    __shared__ int s_baseV, s_baseT;
    int tid = threadIdx.x;
    int row = blockIdx.x * 256 + tid;
    int warp = tid >> 5, lane = tid & 31;
    bool mv = mask_at(m, row);
    unsigned bal = __ballot_sync(0xffffffffu, mv);
    int lpv = __popc(bal & ((1u << lane) - 1));
    int lpt = lane - lpv;
    if (lane == 0) { s_v[warp] = __popc(bal); s_t[warp] = 32 - __popc(bal); }
    __syncthreads();
    if (tid == 0) {
        int av = 0, at = 0;
        #pragma unroll
        for (int w = 0; w < 8; w++) {
            int tv = s_v[w]; s_v[w] = av; av += tv;
            int tt = s_t[w]; s_t[w] = at; at += tt;
        }
        s_baseV = atomicAdd(&g_cv, av);
        s_baseT = atomicAdd(&g_ct, at);
    }
    __syncthreads();
    int pad = (g_nv + 127) & ~127;
    int slot = mv ? (s_baseV + s_v[warp] + lpv)
                  : (pad + s_baseT + s_t[warp] + lpt);
    g_perm[slot] = row;
}

// K3: gather rows via perm, convert to fp16, write A panels in fragment order.
// Panel = 128 rows x 32 k. Block (rb 0..7, ks 0..1) of 16r x 16k, 256 halves,
// stored lane-major: offset = (rb*2+ks)*256 + lane*8 + v, where
//   v = 2*reg + lo;  row = rb*16 + grp + 8*(reg&1);  k = ks*16 + 2*qid + 8*(reg>>1) + lo
__global__ void k3_xconv(const float* __restrict__ x) {
    __shared__ int sperm[BM];
    const int mt = blockIdx.x, kp = blockIdx.y;
    const int tid = threadIdx.x;
    if (tid < BM) sperm[tid] = g_perm[mt * BM + tid];
    __syncthreads();

    __half* dst = g_x + ((size_t)mt * NK + kp) * PANEL_H;
    const int kbase = kp * BK;

    #pragma unroll
    for (int q = 0; q < 2; q++) {
        int h0 = tid * 8 + q * 2048;
        int b = h0 >> 8;                 // 16x16 block
        int rb = b >> 1, ks = b & 1;
        int lane = (h0 >> 3) & 31;
        int grp = lane >> 2, qid = lane & 3;
        __half vals[8];
        #pragma unroll
        for (int reg = 0; reg < 4; reg++) {
            int row = rb * 16 + grp + 8 * (reg & 1);
            int k   = ks * 16 + 2 * qid + 8 * (reg >> 1);
            int src = sperm[row];
            float2 f = (src >= 0)
                ? *(const float2*)(x + (size_t)src * K_DIM + kbase + k)
                : make_float2(0.f, 0.f);
            vals[reg * 2 + 0] = __float2half_rn(f.x);
            vals[reg * 2 + 1] = __float2half_rn(f.y);
        }
        *(uint4*)(dst + h0) = *(const uint4*)vals;
    }
}

// K4: weights -> fp16 B panels in fragment order.
// B block (nb 0..15, ks 0..1) of 8n x 16k, 128 halves:
//   offset = (nb*2+ks)*128 + lane*4 + v; n = nb*8 + grp; k = ks*16 + 2*qid + 8*(v>>1) + (v&1)
__global__ void k4_wconv(const float* __restrict__ Wv, const float* __restrict__ Wt) {
    const int nt = blockIdx.x, kp = blockIdx.y;
    const float* src = blockIdx.z ? Wt : Wv;
    __half* dst = (blockIdx.z ? g_wt : g_wv) + ((size_t)nt * NK + kp) * PANEL_H;
    const int tid = threadIdx.x;
    const int kbase = kp * BK;

    #pragma unroll
    for (int q = 0; q < 2; q++) {
        int h0 = tid * 8 + q * 2048;
        __half vals[8];
        #pragma unroll
        for (int j = 0; j < 8; j++) {
            int h = h0 + j;
            int b = h >> 7;
            int nb = b >> 1, ks = b & 1;
            int lane = (h >> 2) & 31;
            int v = h & 3;
            int grp = lane >> 2, qid = lane & 3;
            int n = nt * 128 + nb * 8 + grp;
            int k = kbase + ks * 16 + 2 * qid + 8 * (v >> 1) + (v & 1);
            vals[j] = __float2half_rn(src[(size_t)n * K_DIM + k]);
        }
        *(uint4*)(dst + h0) = *(const uint4*)vals;
    }
}

// ------------------------------------------------------------- GEMM
extern __shared__ char dsmem[];

__global__ __launch_bounds__(THREADS, 2)
void gemm_kernel(float* __restrict__ out)
{
    const int tid  = threadIdx.x;
    const int warp = tid >> 5;
    const int lane = tid & 31;
    const int grp  = lane >> 2;
    const int qid  = lane & 3;
    const int rb0  = (warp >> 1) * 4;        // A block base (64 rows)
    const int nb0  = (warp & 1) * 8;         // B block base (64 cols)
    const int blockN = blockIdx.x * BN;
    const int mt     = blockIdx.y;

    const int pad = (g_nv + 127) & ~127;
    const char* gA = (const char*)(g_x + (size_t)mt * NK * PANEL_H);
    const char* gB = (const char*)(((mt * BM < pad) ? g_wv : g_wt)
                                   + (size_t)blockIdx.x * NK * PANEL_H);

    const uint32_t sbase = smem_u32(dsmem);

    float acc[4][8][4];
    #pragma unroll
    for (int i = 0; i < 4; i++)
        #pragma unroll
        for (int j = 0; j < 8; j++)
            #pragma unroll
            for (int c = 0; c < 4; c++) acc[i][j][c] = 0.f;

    auto ISSUE = [&](int kt) {
        const uint32_t sst = sbase + (kt & (STAGES - 1)) * STAGE_B;
        const char* srcA = gA + (size_t)kt * APANEL_B;
        const char* srcB = gB + (size_t)kt * APANEL_B;
        #pragma unroll
        for (int i = 0; i < 4; i++) {
            uint32_t off = (uint32_t)(i * 2048 + tid * 16);
            cp16(sst + off, srcA + off);
        }
        #pragma unroll
        for (int i = 0; i < 4; i++) {
            uint32_t off = (uint32_t)(i * 2048 + tid * 16);
            cp16(sst + APANEL_B + off, srcB + off);
        }
        asm volatile("cp.async.commit_group;" ::: "memory");
    };

    auto COMPUTE = [&](int s) {
        const char* sA = dsmem + s * STAGE_B;
        const char* sB = sA + APANEL_B;
        #pragma unroll
        for (int ks = 0; ks < 2; ks++) {
            uint32_t a[4][4];
            #pragma unroll
            for (int i = 0; i < 4; i++) {
                uint4 v = *(const uint4*)(sA + ((rb0 + i) * 2 + ks) * 512 + lane * 16);
                a[i][0] = v.x; a[i][1] = v.y; a[i][2] = v.z; a[i][3] = v.w;
            }
            uint32_t b[8][2];
            #pragma unroll
            for (int j = 0; j < 8; j++) {
                uint2 v = *(const uint2*)(sB + ((nb0 + j) * 2 + ks) * 256 + lane * 8);
                b[j][0] = v.x; b[j][1] = v.y;
            }
            #pragma unroll
            for (int i = 0; i < 4; i++)
                #pragma unroll
                for (int j = 0; j < 8; j++)
                    mma_f16(acc[i][j], a[i], b[j]);
        }
    };

    ISSUE(0); ISSUE(1); ISSUE(2);

    for (int kt = 0; kt < NK; kt++) {
        asm volatile("cp.async.wait_group %0;" :: "n"(STAGES - 2) : "memory");
        __syncthreads();
        if (kt + STAGES - 1 < NK) ISSUE(kt + STAGES - 1);
        COMPUTE(kt & (STAGES - 1));
    }

    // epilogue: scatter rows through perm
    const int blockM = mt * BM;
    #pragma unroll
    for (int i = 0; i < 4; i++) {
        int r = rb0 * 16 + i * 16 + grp;
        int d0 = g_perm[blockM + r];
        int d1 = g_perm[blockM + r + 8];
        #pragma unroll
        for (int j = 0; j < 8; j++) {
            int col = blockN + nb0 * 8 + j * 8 + qid * 2;
            if (d0 >= 0)
                *(float2*)(out + (size_t)d0 * N_DIM + col) =
                    make_float2(acc[i][j][0], acc[i][j][1]);
            if (d1 >= 0)
                *(float2*)(out + (size_t)d1 * N_DIM + col) =
                    make_float2(acc[i][j][2], acc[i][j][3]);
        }
    }
}

// ------------------------------------------------------------- launch
extern "C" void kernel_launch(void* const* d_in, const int* in_sizes, int n_in,
                              void* d_out, int out_size)
{
    const float*         x    = (const float*)d_in[0];
    const unsigned char* mask = (const unsigned char*)d_in[1];
    const float*         Wv   = (const float*)d_in[2];
    const float*         Wt   = (const float*)d_in[3];
    float*               out  = (float*)d_out;

    static bool attr_set = false;
    if (!attr_set) {
        cudaFuncSetAttribute(gemm_kernel,
                             cudaFuncAttributeMaxDynamicSharedMemorySize, DYN_SMEM);
        attr_set = true;
    }

    k0_init<<<1, 1024>>>(mask);
    k1_count<<<M_TOTAL / 256, 256>>>(mask);
    k2_assign<<<M_TOTAL / 256, 256>>>(mask);
    k3_xconv<<<dim3(NMT, NK), 256>>>(x);
    k4_wconv<<<dim3(N_DIM / 128, NK, 2), 256>>>(Wv, Wt);
    gemm_kernel<<<dim3(N_DIM / BN, NMT), THREADS, DYN_SMEM>>>(out);
}